// round 1
// baseline (speedup 1.0000x reference)
#include <cuda_runtime.h>
#include <math.h>
#include <stdint.h>

#define B_  2
#define H_  8
#define T_  2048
#define KD  128
#define BH  (B_*H_)
#define BM  64
#define BN  64
#define NQT (T_/BM)
#define NKT (T_/BN)

// Scratch (device globals; no allocation allowed)
__device__ float d_g [BH*T_];   // g[s] = i[s] - fc[s]
__device__ float d_cm[BH*T_];   // cummax of g
__device__ float d_nf[BH*T_];   // exp(-m[t]) norm floor
__device__ float d_ce[BH*T_];   // exp(g[s] - G_tile(s))
__device__ float d_Gt[BH*NKT];  // per-key-tile max of g

// ---------------------------------------------------------------------------
// Pass 1: per-head scan. fp64 cumsum of log-sigmoid(f), cummax of g, norm
// floor, and per-64-tile column factors. One block (256 thr x 8 elem) per head.
// ---------------------------------------------------------------------------
__global__ void pass1_kernel(const float* __restrict__ ig,
                             const float* __restrict__ fg) {
    const int bh = blockIdx.x, tid = threadIdx.x;
    const float* fp = fg + (size_t)bh * T_;
    const float* ip = ig + (size_t)bh * T_;
    const int base = tid * 8;

    double lf[8]; float gi[8];
#pragma unroll
    for (int r = 0; r < 8; r++) {
        double x = (double)fp[base + r];
        lf[r] = fmin(x, 0.0) - log1p(exp(-fabs(x)));   // log sigmoid, stable
        gi[r] = ip[base + r];
    }
    // thread-local inclusive cumsum
    double run = 0.0, fc[8];
#pragma unroll
    for (int r = 0; r < 8; r++) { run += lf[r]; fc[r] = run; }

    __shared__ double sh[256];
    sh[tid] = run; __syncthreads();
    for (int off = 1; off < 256; off <<= 1) {
        double t = 0.0; if (tid >= off) t = sh[tid - off];
        __syncthreads();
        if (tid >= off) sh[tid] += t;
        __syncthreads();
    }
    double addoff = sh[tid] - run;

    double g[8], gm[8], runm = -1e300;
#pragma unroll
    for (int r = 0; r < 8; r++) {
        fc[r] += addoff;
        g[r]  = (double)gi[r] - fc[r];
        runm  = fmax(runm, g[r]);
        gm[r] = runm;
    }
    __syncthreads();
    sh[tid] = runm; __syncthreads();
    for (int off = 1; off < 256; off <<= 1) {
        double t = -1e300; if (tid >= off) t = sh[tid - off];
        __syncthreads();
        if (tid >= off) sh[tid] = fmax(sh[tid], t);
        __syncthreads();
    }
    double prevmax = (tid == 0) ? -1e300 : sh[tid - 1];

    float gf[8];
#pragma unroll
    for (int r = 0; r < 8; r++) {
        double cm = fmax(prevmax, gm[r]);
        gf[r] = (float)g[r];
        d_g [bh*T_ + base + r] = gf[r];
        d_cm[bh*T_ + base + r] = (float)cm;
        d_nf[bh*T_ + base + r] = (float)exp(-(fc[r] + cm));
    }

    // per-64-element key-tile max of g (tile j = threads 8j..8j+7)
    float lmax = gf[0];
#pragma unroll
    for (int r = 1; r < 8; r++) lmax = fmaxf(lmax, gf[r]);
    __shared__ float shf[256];
    __shared__ float tm[32];
    __syncthreads();
    shf[tid] = lmax; __syncthreads();
    if (tid < 32) {
        float mx = shf[tid * 8];
#pragma unroll
        for (int u = 1; u < 8; u++) mx = fmaxf(mx, shf[tid * 8 + u]);
        tm[tid] = mx;
        d_Gt[bh*NKT + tid] = mx;
    }
    __syncthreads();
    float G = tm[tid >> 3];
#pragma unroll
    for (int r = 0; r < 8; r++)
        d_ce[bh*T_ + base + r] = __expf(gf[r] - G);   // in (0,1]
}

// ---------------------------------------------------------------------------
// Pass 2: main flash-style kernel. One block per (head, 64-row query tile).
// ---------------------------------------------------------------------------
// smem layout (floats):
//   sq [64][128]  q tile, pre-scaled           (broadcast reads)
//   sk [64][132]  k tile, padded               (strided-row float4 reads)
//   sv [64][128]  v tile                       (scalar stride-32 reads)
//   ss [64][68]   staged S, [n][m], padded
//   + 5 x 64 small row vectors
#define SQ_OFF 0
#define SK_OFF (64*128)
#define SV_OFF (SK_OFF + 64*132)
#define SS_OFF (SV_OFF + 64*128)
#define AUX_OFF (SS_OFF + 64*68)
#define SMEM_FLOATS (AUX_OFF + 5*64)

__global__ void __launch_bounds__(256, 1)
mlstm_main(const float* __restrict__ q, const float* __restrict__ k,
           const float* __restrict__ v, float* __restrict__ out) {
    const int bh = blockIdx.x;
    const int qt = (NQT - 1) - blockIdx.y;   // big tiles scheduled first

    extern __shared__ float smem[];
    float* sq   = smem + SQ_OFF;
    float* sk   = smem + SK_OFF;
    float* sv   = smem + SV_OFF;
    float* ss   = smem + SS_OFF;
    float* shcm = smem + AUX_OFF;
    float* shnf = shcm + 64;
    float* shce = shnf + 64;
    float* shg  = shce + 64;
    float* shrs = shg  + 64;

    const int tid = threadIdx.x;
    const int tx = tid & 15, ty = tid >> 4;   // S-stage mapping (16x16)
    const int cx = tid & 31, cy = tid >> 5;   // PV-stage mapping (32x8)
    const float scale = 0.08838834764831845f; // 128^-0.5

    // load q tile (scaled) — coalesced float4
    const float4* qb = (const float4*)(q + ((size_t)bh*T_ + (size_t)qt*BM) * KD);
#pragma unroll
    for (int u = 0; u < 8; u++) {
        int c = tid + u * 256;
        int m = c >> 5, c4 = c & 31;
        float4 val = qb[c];
        val.x *= scale; val.y *= scale; val.z *= scale; val.w *= scale;
        *(float4*)&sq[m*128 + c4*4] = val;
    }
    if (tid < 64) {
        int t0 = bh*T_ + qt*BM + tid;
        shcm[tid] = d_cm[t0];
        shnf[tid] = d_nf[t0];
        shrs[tid] = 0.f;
    }

    float acc[8][4];
#pragma unroll
    for (int i = 0; i < 8; i++)
#pragma unroll
        for (int j = 0; j < 4; j++) acc[i][j] = 0.f;

    __syncthreads();

    for (int kt = 0; kt <= qt; kt++) {
        // ---- load k, v tiles + per-tile vectors ----
        const float4* kb = (const float4*)(k + ((size_t)bh*T_ + (size_t)kt*BN) * KD);
        const float4* vb = (const float4*)(v + ((size_t)bh*T_ + (size_t)kt*BN) * KD);
#pragma unroll
        for (int u = 0; u < 8; u++) {
            int c = tid + u * 256;
            int m = c >> 5, c4 = c & 31;
            *(float4*)&sk[m*132 + c4*4] = kb[c];
            *(float4*)&sv[m*128 + c4*4] = vb[c];
        }
        if (tid < 64) {
            int s0 = bh*T_ + kt*BN + tid;
            shce[tid] = d_ce[s0];
            shg [tid] = d_g [s0];
        }
        __syncthreads();

        // ---- S = (q*scale) . k^T  (rows m = ty+16i, cols n = tx+16j) ----
        float s[4][4];
#pragma unroll
        for (int i = 0; i < 4; i++)
#pragma unroll
            for (int j = 0; j < 4; j++) s[i][j] = 0.f;

#pragma unroll 8
        for (int c4 = 0; c4 < 32; c4++) {
            float4 qv[4], kv[4];
#pragma unroll
            for (int i = 0; i < 4; i++)
                qv[i] = *(const float4*)&sq[(ty + 16*i)*128 + c4*4];
#pragma unroll
            for (int j = 0; j < 4; j++)
                kv[j] = *(const float4*)&sk[(tx + 16*j)*132 + c4*4];
#pragma unroll
            for (int i = 0; i < 4; i++)
#pragma unroll
                for (int j = 0; j < 4; j++) {
                    s[i][j] = fmaf(qv[i].x, kv[j].x, s[i][j]);
                    s[i][j] = fmaf(qv[i].y, kv[j].y, s[i][j]);
                    s[i][j] = fmaf(qv[i].z, kv[j].z, s[i][j]);
                    s[i][j] = fmaf(qv[i].w, kv[j].w, s[i][j]);
                }
        }

        // ---- apply decay matrix D ----
        const float Gtv = d_Gt[bh*NKT + kt];
        if (kt < qt) {
            float rr[4];
#pragma unroll
            for (int i = 0; i < 4; i++)
                rr[i] = __expf(Gtv - shcm[ty + 16*i]);   // <= 1 (G <= cm)
#pragma unroll
            for (int i = 0; i < 4; i++)
#pragma unroll
                for (int j = 0; j < 4; j++)
                    s[i][j] *= rr[i] * shce[tx + 16*j];
        } else {
            // diagonal tile: mask + direct per-element exp (safe, <= 1)
#pragma unroll
            for (int i = 0; i < 4; i++)
#pragma unroll
                for (int j = 0; j < 4; j++) {
                    int m = ty + 16*i, n = tx + 16*j;
                    s[i][j] = (n <= m) ? s[i][j] * __expf(shg[n] - shcm[m]) : 0.f;
                }
        }

        // ---- row sums (warp shuffle over tx) + stage S^T into shared ----
#pragma unroll
        for (int i = 0; i < 4; i++) {
            float p = (s[i][0] + s[i][1]) + (s[i][2] + s[i][3]);
            p += __shfl_xor_sync(0xffffffffu, p, 1);
            p += __shfl_xor_sync(0xffffffffu, p, 2);
            p += __shfl_xor_sync(0xffffffffu, p, 4);
            p += __shfl_xor_sync(0xffffffffu, p, 8);
            if (tx == 0) shrs[ty + 16*i] += p;   // one writer per row
#pragma unroll
            for (int j = 0; j < 4; j++)
                ss[(tx + 16*j)*68 + ty + 16*i] = s[i][j];
        }
        __syncthreads();

        // ---- h += S @ v  (rows m = 8cy+i, cols vc = cx+32j) ----
#pragma unroll 8
        for (int n = 0; n < 64; n++) {
            float4 a0 = *(const float4*)&ss[n*68 + cy*8];
            float4 a1 = *(const float4*)&ss[n*68 + cy*8 + 4];
            float av[8] = {a0.x, a0.y, a0.z, a0.w, a1.x, a1.y, a1.z, a1.w};
            float bv[4];
#pragma unroll
            for (int j = 0; j < 4; j++) bv[j] = sv[n*128 + cx + 32*j];
#pragma unroll
            for (int i = 0; i < 8; i++)
#pragma unroll
                for (int j = 0; j < 4; j++)
                    acc[i][j] = fmaf(av[i], bv[j], acc[i][j]);
        }
        __syncthreads();
    }

    // ---- normalize and write ----
    float* ob = out + ((size_t)bh*T_ + (size_t)qt*BM) * KD;
#pragma unroll
    for (int i = 0; i < 8; i++) {
        int m = cy*8 + i;
        float nr  = fmaxf(fabsf(shrs[m]), shnf[m]);
        float inv = 1.0f / nr;
#pragma unroll
        for (int j = 0; j < 4; j++)
            ob[(size_t)m*KD + cx + 32*j] = acc[i][j] * inv;
    }
}

// ---------------------------------------------------------------------------
extern "C" void kernel_launch(void* const* d_in, const int* in_sizes, int n_in,
                              void* d_out, int out_size) {
    const float* q  = (const float*)d_in[0];
    const float* k  = (const float*)d_in[1];
    const float* v  = (const float*)d_in[2];
    const float* ig = (const float*)d_in[3];
    const float* fg = (const float*)d_in[4];
    float* out = (float*)d_out;

    pass1_kernel<<<BH, 256>>>(ig, fg);

    const int smem_bytes = SMEM_FLOATS * (int)sizeof(float);
    cudaFuncSetAttribute(mlstm_main,
                         cudaFuncAttributeMaxDynamicSharedMemorySize,
                         smem_bytes);
    dim3 grid(BH, NQT);
    mlstm_main<<<grid, 256, smem_bytes>>>(q, k, v, out);
}

// round 3
// speedup vs baseline: 2.9693x; 2.9693x over previous
#include <cuda_runtime.h>
#include <cuda_bf16.h>
#include <math.h>
#include <stdint.h>

#define B_  2
#define H_  8
#define T_  2048
#define KD  128
#define BH  (B_*H_)
#define BN  64
#define NKT (T_/BN)     // 32
#define NQT (T_/128)    // 16
#define NELEM (BH*T_*KD)

// ---------------- device-global scratch (no runtime alloc allowed) --------
__device__ float d_g [BH*T_];
__device__ float d_cm[BH*T_];
__device__ float d_nf[BH*T_];
__device__ float d_ce[BH*T_];
__device__ float d_Gt[BH*NKT];

__device__ __nv_bfloat16 d_kh[NELEM], d_kl[NELEM];
__device__ __nv_bfloat16 d_vh[NELEM], d_vl[NELEM];

// ---------------- helpers -------------------------------------------------
__device__ __forceinline__ uint32_t smem_u32(const void* p) {
    uint32_t a;
    asm("{ .reg .u64 t; cvta.to.shared.u64 t, %1; cvt.u32.u64 %0, t; }"
        : "=r"(a) : "l"(p));
    return a;
}

#define CP16(dst, src) \
    asm volatile("cp.async.cg.shared.global [%0], [%1], 16;" :: "r"(dst), "l"(src))
#define CP_COMMIT() asm volatile("cp.async.commit_group;" ::: "memory")
#define CP_WAIT0()  asm volatile("cp.async.wait_group 0;" ::: "memory")

__device__ __forceinline__ void ldm_x4(uint32_t (&r)[4], uint32_t addr) {
    asm volatile("ldmatrix.sync.aligned.m8n8.x4.shared.b16 {%0,%1,%2,%3}, [%4];"
        : "=r"(r[0]), "=r"(r[1]), "=r"(r[2]), "=r"(r[3]) : "r"(addr));
}
__device__ __forceinline__ void ldm_x4_t(uint32_t (&r)[4], uint32_t addr) {
    asm volatile("ldmatrix.sync.aligned.m8n8.x4.trans.shared.b16 {%0,%1,%2,%3}, [%4];"
        : "=r"(r[0]), "=r"(r[1]), "=r"(r[2]), "=r"(r[3]) : "r"(addr));
}
__device__ __forceinline__ void mma16816(float (&d)[4], const uint32_t (&a)[4],
                                         uint32_t b0, uint32_t b1) {
    asm volatile(
        "mma.sync.aligned.m16n8k16.row.col.f32.bf16.bf16.f32 "
        "{%0,%1,%2,%3}, {%4,%5,%6,%7}, {%8,%9}, {%0,%1,%2,%3};"
        : "+f"(d[0]), "+f"(d[1]), "+f"(d[2]), "+f"(d[3])
        : "r"(a[0]), "r"(a[1]), "r"(a[2]), "r"(a[3]), "r"(b0), "r"(b1));
}

// split two fp32 into packed bf16x2 (hi plane, lo plane); low 16 bits = first
__device__ __forceinline__ void split2(float a, float b, uint32_t& h, uint32_t& l) {
    __nv_bfloat16 ah = __float2bfloat16(a);
    __nv_bfloat16 bh = __float2bfloat16(b);
    __nv_bfloat16 al = __float2bfloat16(a - __bfloat162float(ah));
    __nv_bfloat16 bl = __float2bfloat16(b - __bfloat162float(bh));
    h = (uint32_t)__bfloat16_as_ushort(ah) | ((uint32_t)__bfloat16_as_ushort(bh) << 16);
    l = (uint32_t)__bfloat16_as_ushort(al) | ((uint32_t)__bfloat16_as_ushort(bl) << 16);
}

// swizzled chunk offset within a tile: 16 chunks (16B each) per 256B row
__device__ __forceinline__ uint32_t swzo(int row, int ck) {
    return (uint32_t)((row * 16 + (ck ^ (row & 7))) << 4);
}

// ---------------- smem layout (bytes) -------------------------------------
#define OFF_QH   0
#define OFF_QL   32768
#define OFF_TILE(b) (65536 + (b) * 65536)
#define OFF_KH   0
#define OFF_KL   16384
#define OFF_VH   32768
#define OFF_VL   49152
#define OFF_CE   196608
#define OFF_G    197120
#define SMEM_TOTAL 197632

// ---------------------------------------------------------------------------
// Pass 1: per-head gate scan (fp32 transcendentals, fp64 accumulation)
// ---------------------------------------------------------------------------
__global__ void pass1_kernel(const float* __restrict__ ig,
                             const float* __restrict__ fg) {
    const int bh = blockIdx.x, tid = threadIdx.x;
    const float* fp = fg + (size_t)bh * T_;
    const float* ip = ig + (size_t)bh * T_;
    const int base = tid * 8;

    double lf[8]; float gi[8];
#pragma unroll
    for (int r = 0; r < 8; r++) {
        float x = fp[base + r];
        lf[r] = (double)(fminf(x, 0.f) - log1pf(__expf(-fabsf(x))));
        gi[r] = ip[base + r];
    }
    double run = 0.0, fc[8];
#pragma unroll
    for (int r = 0; r < 8; r++) { run += lf[r]; fc[r] = run; }

    __shared__ double sh[256];
    sh[tid] = run; __syncthreads();
    for (int off = 1; off < 256; off <<= 1) {
        double t = 0.0; if (tid >= off) t = sh[tid - off];
        __syncthreads();
        if (tid >= off) sh[tid] += t;
        __syncthreads();
    }
    double addoff = sh[tid] - run;

    double g[8], gm[8], runm = -1e300;
#pragma unroll
    for (int r = 0; r < 8; r++) {
        fc[r] += addoff;
        g[r]  = (double)gi[r] - fc[r];
        runm  = fmax(runm, g[r]);
        gm[r] = runm;
    }
    __syncthreads();
    sh[tid] = runm; __syncthreads();
    for (int off = 1; off < 256; off <<= 1) {
        double t = -1e300; if (tid >= off) t = sh[tid - off];
        __syncthreads();
        if (tid >= off) sh[tid] = fmax(sh[tid], t);
        __syncthreads();
    }
    double prevmax = (tid == 0) ? -1e300 : sh[tid - 1];

    float gf[8];
#pragma unroll
    for (int r = 0; r < 8; r++) {
        double cm = fmax(prevmax, gm[r]);
        gf[r] = (float)g[r];
        d_g [bh*T_ + base + r] = gf[r];
        d_cm[bh*T_ + base + r] = (float)cm;
        d_nf[bh*T_ + base + r] = __expf((float)(-(fc[r] + cm)));
    }

    float lmax = gf[0];
#pragma unroll
    for (int r = 1; r < 8; r++) lmax = fmaxf(lmax, gf[r]);
    __shared__ float shf[256];
    __shared__ float tm[32];
    __syncthreads();
    shf[tid] = lmax; __syncthreads();
    if (tid < 32) {
        float mx = shf[tid * 8];
#pragma unroll
        for (int u = 1; u < 8; u++) mx = fmaxf(mx, shf[tid * 8 + u]);
        tm[tid] = mx;
        d_Gt[bh*NKT + tid] = mx;
    }
    __syncthreads();
    float G = tm[tid >> 3];
#pragma unroll
    for (int r = 0; r < 8; r++)
        d_ce[bh*T_ + base + r] = __expf(gf[r] - G);
}

// ---------------------------------------------------------------------------
// Split K, V into bf16 (hi, lo) planes
// ---------------------------------------------------------------------------
__global__ void split_kv(const float* __restrict__ k, const float* __restrict__ v) {
    int i = blockIdx.x * 256 + threadIdx.x;   // one float4 each
    float4 kv = ((const float4*)k)[i];
    float4 vv = ((const float4*)v)[i];
    uint32_t h0, l0, h1, l1;
    split2(kv.x, kv.y, h0, l0); split2(kv.z, kv.w, h1, l1);
    ((uint2*)d_kh)[i] = make_uint2(h0, h1);
    ((uint2*)d_kl)[i] = make_uint2(l0, l1);
    split2(vv.x, vv.y, h0, l0); split2(vv.z, vv.w, h1, l1);
    ((uint2*)d_vh)[i] = make_uint2(h0, h1);
    ((uint2*)d_vl)[i] = make_uint2(l0, l1);
}

// ---------------------------------------------------------------------------
// Main kernel: 256 threads (8 warps), BM=128, BN=64, mma.sync bf16 3-chain
// ---------------------------------------------------------------------------
__device__ __forceinline__ void load_tile(char* smem, uint32_t sb, int b,
                                          int bh, int kt, int tid) {
    size_t gbase = ((size_t)(bh * T_ + kt * 64)) * KD;
    const char* gkh = (const char*)d_kh + gbase * 2;
    const char* gkl = (const char*)d_kl + gbase * 2;
    const char* gvh = (const char*)d_vh + gbase * 2;
    const char* gvl = (const char*)d_vl + gbase * 2;
    uint32_t tb = sb + OFF_TILE(b);
#pragma unroll
    for (int u = 0; u < 4; u++) {
        int ch = tid + u * 256;            // 0..1023
        int r = ch >> 4, c = ch & 15;
        uint32_t a = swzo(r, c);
        size_t go = (size_t)ch * 16;       // r*256 + c*16
        CP16(tb + OFF_KH + a, gkh + go);
        CP16(tb + OFF_KL + a, gkl + go);
        CP16(tb + OFF_VH + a, gvh + go);
        CP16(tb + OFF_VL + a, gvl + go);
    }
    if (tid < 16) {
        CP16(sb + OFF_CE + b * 256 + tid * 16,
             (const char*)(d_ce + bh * T_ + kt * 64) + tid * 16);
    } else if (tid < 32) {
        CP16(sb + OFF_G + b * 256 + (tid - 16) * 16,
             (const char*)(d_g + bh * T_ + kt * 64) + (tid - 16) * 16);
    }
}

__global__ void __launch_bounds__(256, 1)
mlstm_mma(const float* __restrict__ q, float* __restrict__ out) {
    extern __shared__ char smem[];
    const uint32_t sb = smem_u32(smem);
    const int tid  = threadIdx.x;
    const int lane = tid & 31;
    const int wid  = tid >> 5;
    const int m0   = wid * 16;
    const int bid  = blockIdx.x;
    const int bh   = bid & 15;
    const int qt   = (NQT - 1) - (bid >> 4);   // big tiles first
    const int NT   = 2 * qt + 2;

    // start tile 0 fetch immediately
    load_tile(smem, sb, 0, bh, 0, tid);
    CP_COMMIT();

    // ---- prologue: split Q into smem planes (scaled) ----
    const float scale = 0.08838834764831845f;
    const float* qbase = q + (size_t)(bh * T_ + qt * 128) * KD;
#pragma unroll
    for (int u = 0; u < 8; u++) {
        int ch = tid + u * 256;            // 0..2047
        int r = ch >> 4, c = ch & 15;
        const float4* src = (const float4*)(qbase + r * 128 + c * 8);
        float4 x0 = src[0], x1 = src[1];
        uint32_t h0, l0, h1, l1, h2, l2, h3, l3;
        split2(x0.x * scale, x0.y * scale, h0, l0);
        split2(x0.z * scale, x0.w * scale, h1, l1);
        split2(x1.x * scale, x1.y * scale, h2, l2);
        split2(x1.z * scale, x1.w * scale, h3, l3);
        uint32_t a = swzo(r, c);
        *(uint4*)(smem + OFF_QH + a) = make_uint4(h0, h1, h2, h3);
        *(uint4*)(smem + OFF_QL + a) = make_uint4(l0, l1, l2, l3);
    }

    const int rowg0 = qt * 128 + m0 + (lane >> 2);
    const int rowg1 = rowg0 + 8;
    const float cm0 = d_cm[bh * T_ + rowg0];
    const float cm1 = d_cm[bh * T_ + rowg1];

    float hacc[16][4];
#pragma unroll
    for (int i = 0; i < 16; i++)
#pragma unroll
        for (int j = 0; j < 4; j++) hacc[i][j] = 0.f;
    float rs0 = 0.f, rs1 = 0.f;

    CP_WAIT0();
    __syncthreads();

    for (int kt = 0; kt < NT; kt++) {
        const int b = kt & 1;
        if (kt + 1 < NT) { load_tile(smem, sb, 1 - b, bh, kt + 1, tid); CP_COMMIT(); }
        const float Gtv = d_Gt[bh * NKT + kt];
        const uint32_t tb = sb + OFF_TILE(b);

        // ---- S = Qs . K^T (3 bf16 chains) ----
        float sa[8][4];
#pragma unroll
        for (int i = 0; i < 8; i++)
#pragma unroll
            for (int j = 0; j < 4; j++) sa[i][j] = 0.f;

#pragma unroll
        for (int kb = 0; kb < 8; kb++) {
            uint32_t aqh[4], aql[4];
            {
                int row = m0 + (lane & 15);
                int ck  = 2 * kb + (lane >> 4);
                ldm_x4(aqh, sb + OFF_QH + swzo(row, ck));
                ldm_x4(aql, sb + OFF_QL + swzo(row, ck));
            }
#pragma unroll
            for (int np = 0; np < 4; np++) {
                uint32_t bh4[4], bl4[4];
                {
                    int row = 16 * np + (lane & 7) + ((lane >> 4) << 3);
                    int ck  = 2 * kb + ((lane >> 3) & 1);
                    ldm_x4(bh4, tb + OFF_KH + swzo(row, ck));
                    ldm_x4(bl4, tb + OFF_KL + swzo(row, ck));
                }
                mma16816(sa[2*np],   aqh, bh4[0], bh4[1]);
                mma16816(sa[2*np+1], aqh, bh4[2], bh4[3]);
                mma16816(sa[2*np],   aql, bh4[0], bh4[1]);
                mma16816(sa[2*np+1], aql, bh4[2], bh4[3]);
                mma16816(sa[2*np],   aqh, bl4[0], bl4[1]);
                mma16816(sa[2*np+1], aqh, bl4[2], bl4[3]);
            }
        }

        // ---- decay + rowsum + split P into A fragments (in registers) ----
        const float* ce = (const float*)(smem + OFF_CE + b * 256);
        const float* gg = (const float*)(smem + OFF_G  + b * 256);
        const bool diag = (kt >= 2 * qt);
        const float rr0 = __expf(Gtv - cm0);
        const float rr1 = __expf(Gtv - cm1);
        uint32_t phf[4][4], plf[4][4];
#pragma unroll
        for (int nb = 0; nb < 8; nb++) {
            int n0 = 8 * nb + 2 * (lane & 3);
            float p0, p1, p2, p3;
            if (!diag) {
                float c0 = ce[n0], c1 = ce[n0 + 1];
                p0 = sa[nb][0] * rr0 * c0; p1 = sa[nb][1] * rr0 * c1;
                p2 = sa[nb][2] * rr1 * c0; p3 = sa[nb][3] * rr1 * c1;
            } else {
                int s0g = kt * 64 + n0;
                float g0 = gg[n0], g1 = gg[n0 + 1];
                p0 = (s0g     <= rowg0) ? sa[nb][0] * __expf(g0 - cm0) : 0.f;
                p1 = (s0g + 1 <= rowg0) ? sa[nb][1] * __expf(g1 - cm0) : 0.f;
                p2 = (s0g     <= rowg1) ? sa[nb][2] * __expf(g0 - cm1) : 0.f;
                p3 = (s0g + 1 <= rowg1) ? sa[nb][3] * __expf(g1 - cm1) : 0.f;
            }
            rs0 += p0 + p1; rs1 += p2 + p3;
            int kf = nb >> 1, hx = (nb & 1) * 2;
            split2(p0, p1, phf[kf][hx],     plf[kf][hx]);
            split2(p2, p3, phf[kf][hx + 1], plf[kf][hx + 1]);
        }

        // ---- H += P . V (3 bf16 chains) ----
#pragma unroll
        for (int kf = 0; kf < 4; kf++) {
#pragma unroll
            for (int np = 0; np < 8; np++) {
                uint32_t vh4[4], vl4[4];
                {
                    int row = 16 * kf + (lane & 7) + (((lane >> 3) & 1) << 3);
                    int ck  = 2 * np + (lane >> 4);
                    ldm_x4_t(vh4, tb + OFF_VH + swzo(row, ck));
                    ldm_x4_t(vl4, tb + OFF_VL + swzo(row, ck));
                }
                mma16816(hacc[2*np],   phf[kf], vh4[0], vh4[1]);
                mma16816(hacc[2*np+1], phf[kf], vh4[2], vh4[3]);
                mma16816(hacc[2*np],   phf[kf], vl4[0], vl4[1]);
                mma16816(hacc[2*np+1], phf[kf], vl4[2], vl4[3]);
                mma16816(hacc[2*np],   plf[kf], vh4[0], vh4[1]);
                mma16816(hacc[2*np+1], plf[kf], vh4[2], vh4[3]);
            }
        }

        CP_WAIT0();
        __syncthreads();
    }

    // ---- reduce rowsums, normalize, write ----
    rs0 += __shfl_xor_sync(0xffffffffu, rs0, 1);
    rs0 += __shfl_xor_sync(0xffffffffu, rs0, 2);
    rs1 += __shfl_xor_sync(0xffffffffu, rs1, 1);
    rs1 += __shfl_xor_sync(0xffffffffu, rs1, 2);
    const float nf0 = d_nf[bh * T_ + rowg0];
    const float nf1 = d_nf[bh * T_ + rowg1];
    const float inv0 = 1.f / fmaxf(fabsf(rs0), nf0);
    const float inv1 = 1.f / fmaxf(fabsf(rs1), nf1);
    float* o0 = out + ((size_t)(bh * T_ + rowg0)) * KD;
    float* o1 = out + ((size_t)(bh * T_ + rowg1)) * KD;
#pragma unroll
    for (int nb = 0; nb < 16; nb++) {
        int c = 8 * nb + 2 * (lane & 3);
        *(float2*)(o0 + c) = make_float2(hacc[nb][0] * inv0, hacc[nb][1] * inv0);
        *(float2*)(o1 + c) = make_float2(hacc[nb][2] * inv1, hacc[nb][3] * inv1);
    }
}

// ---------------------------------------------------------------------------
extern "C" void kernel_launch(void* const* d_in, const int* in_sizes, int n_in,
                              void* d_out, int out_size) {
    const float* q  = (const float*)d_in[0];
    const float* k  = (const float*)d_in[1];
    const float* v  = (const float*)d_in[2];
    const float* ig = (const float*)d_in[3];
    const float* fg = (const float*)d_in[4];
    float* out = (float*)d_out;

    split_kv<<<NELEM / 4 / 256, 256>>>(k, v);
    pass1_kernel<<<BH, 256>>>(ig, fg);

    cudaFuncSetAttribute(mlstm_mma,
                         cudaFuncAttributeMaxDynamicSharedMemorySize, SMEM_TOTAL);
    mlstm_mma<<<BH * NQT, 256, SMEM_TOTAL>>>(q, out);
}